// round 4
// baseline (speedup 1.0000x reference)
#include <cuda_runtime.h>
#include <cuda_bf16.h>
#include <math_constants.h>

#define NN 50000
#define NE 800000
#define FIN 256
#define OALL 256   /* HEADS*OUT = 4*64 */

// ---------------- scratch (static device globals; no allocation) -------------
__device__ __align__(16) float g_xh[NN * OALL];      // projected features [N,256]
__device__ __align__(16) float g_asrc[NN * 4];
__device__ __align__(16) float g_adst[NN * 4];
__device__ __align__(16) float g_amax[NN * 4];
__device__ __align__(16) float g_asum[NN * 4];
__device__ __align__(16) float g_alphaE[NE * 4];     // per-edge per-head values

// ---------------- helpers ----------------------------------------------------
__device__ __forceinline__ void atomicMaxF(float* addr, float v) {
    if (v >= 0.f) atomicMax((int*)addr, __float_as_int(v));
    else          atomicMin((unsigned int*)addr, __float_as_uint(v));
}

__device__ __forceinline__ void redAdd4(float* p, float4 v) {
    asm volatile("red.global.add.v4.f32 [%0], {%1,%2,%3,%4};"
                 :: "l"(p), "f"(v.x), "f"(v.y), "f"(v.z), "f"(v.w) : "memory");
}

// ---------------- k0: init out=bias, amax=-inf, asum=0 ----------------------
__global__ void init_kernel(float* __restrict__ out, const float* __restrict__ bias) {
    int n = blockIdx.x;
    int t = threadIdx.x;
    out[n * OALL + t] = bias[t];
    if (t < 4) {
        g_amax[n * 4 + t] = -CUDART_INF_F;
        g_asum[n * 4 + t] = 0.f;
    }
}

// ---------------- k1: xh = x @ W  (W[h][f][c] -> col o = h*64+c) -------------
__global__ void gemm_kernel(const float* __restrict__ x, const float* __restrict__ w) {
    __shared__ __align__(16) float xs[64][33];
    __shared__ __align__(16) float ws[32][256];
    int tid = threadIdx.x;
    int tx = tid & 63;      // col group: cols tx*4 .. tx*4+3
    int ty = tid >> 6;      // 0..3 : rows ty*16 .. +15
    int rowBase = blockIdx.x * 64;

    float acc[16][4];
#pragma unroll
    for (int r = 0; r < 16; r++)
#pragma unroll
        for (int j = 0; j < 4; j++) acc[r][j] = 0.f;

    int lr  = tid >> 3;          // loader row 0..31
    int lk  = (tid & 7) * 4;     // loader k offset
    int wo  = (tid & 63) * 4;    // loader out-col
    int wh  = wo >> 6;           // head
    int wc  = wo & 63;           // chan within head
    int wk0 = tid >> 6;          // 0..3

    for (int k0 = 0; k0 < FIN; k0 += 32) {
        // x tile: 64 rows x 32 k
#pragma unroll
        for (int p = 0; p < 2; p++) {
            int row = lr + p * 32;
            int grow = rowBase + row;
            float4 v = make_float4(0.f, 0.f, 0.f, 0.f);
            if (grow < NN) v = *(const float4*)(x + (long)grow * FIN + k0 + lk);
            xs[row][lk + 0] = v.x; xs[row][lk + 1] = v.y;
            xs[row][lk + 2] = v.z; xs[row][lk + 3] = v.w;
        }
        // w tile: 32 k x 256 cols ; W layout [4][256][64]
#pragma unroll
        for (int p = 0; p < 8; p++) {
            int kk = wk0 + p * 4;
            float4 v = *(const float4*)(w + wh * (FIN * 64) + (k0 + kk) * 64 + wc);
            *(float4*)&ws[kk][wo] = v;
        }
        __syncthreads();
#pragma unroll 4
        for (int kk = 0; kk < 32; kk++) {
            float4 b = *(const float4*)&ws[kk][tx * 4];
#pragma unroll
            for (int r = 0; r < 16; r++) {
                float a = xs[ty * 16 + r][kk];
                acc[r][0] += a * b.x; acc[r][1] += a * b.y;
                acc[r][2] += a * b.z; acc[r][3] += a * b.w;
            }
        }
        __syncthreads();
    }
#pragma unroll
    for (int r = 0; r < 16; r++) {
        int grow = rowBase + ty * 16 + r;
        if (grow < NN) {
            float4 v = make_float4(acc[r][0], acc[r][1], acc[r][2], acc[r][3]);
            *(float4*)(g_xh + (long)grow * OALL + tx * 4) = v;
        }
    }
}

// ---------------- k2: alpha_src/dst[n,h] = <xh[n,h,:], att[h,:]> -------------
__global__ void alpha_kernel(const float* __restrict__ att_s, const float* __restrict__ att_d) {
    int n = blockIdx.x * 8 + (threadIdx.x >> 5);
    if (n >= NN) return;
    int lane = threadIdx.x & 31;
    int base = lane * 8;                 // = h*64 + (lane&7)*8, h = lane>>3
    int h = lane >> 3;

    const float4* xr = (const float4*)(g_xh + (long)n * OALL + base);
    const float4* sa = (const float4*)(att_s + base);
    const float4* da = (const float4*)(att_d + base);
    float4 v0 = xr[0], v1 = xr[1];
    float4 s0 = sa[0], s1 = sa[1];
    float4 d0 = da[0], d1 = da[1];

    float s = v0.x * s0.x + v0.y * s0.y + v0.z * s0.z + v0.w * s0.w
            + v1.x * s1.x + v1.y * s1.y + v1.z * s1.z + v1.w * s1.w;
    float d = v0.x * d0.x + v0.y * d0.y + v0.z * d0.z + v0.w * d0.w
            + v1.x * d1.x + v1.y * d1.y + v1.z * d1.z + v1.w * d1.w;
#pragma unroll
    for (int o = 4; o; o >>= 1) {
        s += __shfl_xor_sync(0xffffffffu, s, o);
        d += __shfl_xor_sync(0xffffffffu, d, o);
    }
    if ((lane & 7) == 0) {
        g_asrc[n * 4 + h] = s;
        g_adst[n * 4 + h] = d;
    }
}

// ---------------- k3: per-edge leaky_relu logits + segment max ---------------
__global__ void edge_max_kernel(const int* __restrict__ ei) {
    int e = blockIdx.x * 256 + threadIdx.x;
    if (e >= NE) return;
    int r = ei[e];
    int c = ei[NE + e];
    float4 s = *(const float4*)(g_asrc + r * 4);
    float4 d = *(const float4*)(g_adst + c * 4);
    float4 a;
    a.x = s.x + d.x; a.y = s.y + d.y; a.z = s.z + d.z; a.w = s.w + d.w;
    a.x = a.x > 0.f ? a.x : 0.2f * a.x;
    a.y = a.y > 0.f ? a.y : 0.2f * a.y;
    a.z = a.z > 0.f ? a.z : 0.2f * a.z;
    a.w = a.w > 0.f ? a.w : 0.2f * a.w;
    *(float4*)(g_alphaE + (long)e * 4) = a;
    atomicMaxF(g_amax + r * 4 + 0, a.x);
    atomicMaxF(g_amax + r * 4 + 1, a.y);
    atomicMaxF(g_amax + r * 4 + 2, a.z);
    atomicMaxF(g_amax + r * 4 + 3, a.w);
}

// ---------------- k4: exp(a - max), segment sum ------------------------------
__global__ void edge_exp_kernel(const int* __restrict__ ei) {
    int e = blockIdx.x * 256 + threadIdx.x;
    if (e >= NE) return;
    int r = ei[e];
    float4 a = *(const float4*)(g_alphaE + (long)e * 4);
    float4 m = *(const float4*)(g_amax + r * 4);
    float4 ex;
    ex.x = expf(a.x - m.x);
    ex.y = expf(a.y - m.y);
    ex.z = expf(a.z - m.z);
    ex.w = expf(a.w - m.w);
    *(float4*)(g_alphaE + (long)e * 4) = ex;
    redAdd4(g_asum + r * 4, ex);
}

// ---------------- k5: message scatter (warp per edge) ------------------------
__global__ void msg_kernel(const int* __restrict__ ei, float* __restrict__ out) {
    int e = blockIdx.x * 8 + (threadIdx.x >> 5);
    if (e >= NE) return;
    int lane = threadIdx.x & 31;
    int r = ei[e];
    int c = ei[NE + e];
    int h = lane >> 3;

    float ae = g_alphaE[(long)e * 4 + h];
    float s  = g_asum[r * 4 + h];
    float coef = ae / fmaxf(s, 1e-16f);

    const float4* src = (const float4*)(g_xh + (long)c * OALL + lane * 8);
    float4 v0 = src[0], v1 = src[1];
    v0.x *= coef; v0.y *= coef; v0.z *= coef; v0.w *= coef;
    v1.x *= coef; v1.y *= coef; v1.z *= coef; v1.w *= coef;

    float* dst = out + (long)r * OALL + lane * 8;
    redAdd4(dst, v0);
    redAdd4(dst + 4, v1);
}

// -----------------------------------------------------------------------------
extern "C" void kernel_launch(void* const* d_in, const int* in_sizes, int n_in,
                              void* d_out, int out_size) {
    const float* x     = (const float*)d_in[0];
    const int*   ei    = (const int*)d_in[1];
    const float* w     = (const float*)d_in[2];
    const float* att_s = (const float*)d_in[3];
    const float* att_d = (const float*)d_in[4];
    const float* bias  = (const float*)d_in[5];
    float* out = (float*)d_out;

    init_kernel<<<NN, 256>>>(out, bias);
    gemm_kernel<<<(NN + 63) / 64, 256>>>(x, w);
    alpha_kernel<<<(NN + 7) / 8, 256>>>(att_s, att_d);
    edge_max_kernel<<<(NE + 255) / 256, 256>>>(ei);
    edge_exp_kernel<<<(NE + 255) / 256, 256>>>(ei);
    msg_kernel<<<(NE + 7) / 8, 256>>>(ei, out);
}

// round 5
// speedup vs baseline: 1.6391x; 1.6391x over previous
#include <cuda_runtime.h>
#include <cuda_bf16.h>
#include <math_constants.h>

#define NN 50000
#define NE 800000
#define FIN 256
#define OALL 256   /* HEADS*OUT = 4*64 */
#define NB 196     /* ceil(NN/256) */

// ---------------- scratch (static device globals; no allocation) -------------
__device__ __align__(16) float g_xh[NN * OALL];      // projected features [N,256]
__device__ __align__(16) float g_asrc[NN * 4];
__device__ __align__(16) float g_adst[NN * 4];
__device__ int g_deg[NN];
__device__ int g_rowptr[NN + 1];
__device__ int g_cur[NN];
__device__ int g_part[NB];
__device__ int g_poff[NB];
__device__ int g_ecol[NE];

// ---------------- k1: xh = x @ W  (W[h][f][c] -> col o = h*64+c) -------------
__global__ void gemm_kernel(const float* __restrict__ x, const float* __restrict__ w) {
    __shared__ __align__(16) float xs[64][33];
    __shared__ __align__(16) float ws[32][256];
    int tid = threadIdx.x;
    int tx = tid & 63;
    int ty = tid >> 6;
    int rowBase = blockIdx.x * 64;

    float acc[16][4];
#pragma unroll
    for (int r = 0; r < 16; r++)
#pragma unroll
        for (int j = 0; j < 4; j++) acc[r][j] = 0.f;

    int lr  = tid >> 3;
    int lk  = (tid & 7) * 4;
    int wo  = (tid & 63) * 4;
    int wh  = wo >> 6;
    int wc  = wo & 63;
    int wk0 = tid >> 6;

    for (int k0 = 0; k0 < FIN; k0 += 32) {
#pragma unroll
        for (int p = 0; p < 2; p++) {
            int row = lr + p * 32;
            int grow = rowBase + row;
            float4 v = make_float4(0.f, 0.f, 0.f, 0.f);
            if (grow < NN) v = *(const float4*)(x + (long)grow * FIN + k0 + lk);
            xs[row][lk + 0] = v.x; xs[row][lk + 1] = v.y;
            xs[row][lk + 2] = v.z; xs[row][lk + 3] = v.w;
        }
#pragma unroll
        for (int p = 0; p < 8; p++) {
            int kk = wk0 + p * 4;
            float4 v = *(const float4*)(w + wh * (FIN * 64) + (k0 + kk) * 64 + wc);
            *(float4*)&ws[kk][wo] = v;
        }
        __syncthreads();
#pragma unroll 4
        for (int kk = 0; kk < 32; kk++) {
            float4 b = *(const float4*)&ws[kk][tx * 4];
#pragma unroll
            for (int r = 0; r < 16; r++) {
                float a = xs[ty * 16 + r][kk];
                acc[r][0] += a * b.x; acc[r][1] += a * b.y;
                acc[r][2] += a * b.z; acc[r][3] += a * b.w;
            }
        }
        __syncthreads();
    }
#pragma unroll
    for (int r = 0; r < 16; r++) {
        int grow = rowBase + ty * 16 + r;
        if (grow < NN) {
            float4 v = make_float4(acc[r][0], acc[r][1], acc[r][2], acc[r][3]);
            *(float4*)(g_xh + (long)grow * OALL + tx * 4) = v;
        }
    }
}

// ---------------- k2: alpha_src/dst[n,h] = <xh[n,h,:], att[h,:]> -------------
__global__ void alpha_kernel(const float* __restrict__ att_s, const float* __restrict__ att_d) {
    int n = blockIdx.x * 8 + (threadIdx.x >> 5);
    if (n >= NN) return;
    int lane = threadIdx.x & 31;
    int base = lane * 8;
    int h = lane >> 3;

    const float4* xr = (const float4*)(g_xh + (long)n * OALL + base);
    const float4* sa = (const float4*)(att_s + base);
    const float4* da = (const float4*)(att_d + base);
    float4 v0 = xr[0], v1 = xr[1];
    float4 s0 = sa[0], s1 = sa[1];
    float4 d0 = da[0], d1 = da[1];

    float s = v0.x * s0.x + v0.y * s0.y + v0.z * s0.z + v0.w * s0.w
            + v1.x * s1.x + v1.y * s1.y + v1.z * s1.z + v1.w * s1.w;
    float d = v0.x * d0.x + v0.y * d0.y + v0.z * d0.z + v0.w * d0.w
            + v1.x * d1.x + v1.y * d1.y + v1.z * d1.z + v1.w * d1.w;
#pragma unroll
    for (int o = 4; o; o >>= 1) {
        s += __shfl_xor_sync(0xffffffffu, s, o);
        d += __shfl_xor_sync(0xffffffffu, d, o);
    }
    if ((lane & 7) == 0) {
        g_asrc[n * 4 + h] = s;
        g_adst[n * 4 + h] = d;
    }
}

// ---------------- CSR build --------------------------------------------------
__global__ void zero_deg_kernel() {
    int i = blockIdx.x * 256 + threadIdx.x;
    if (i < NN) g_deg[i] = 0;
}

__global__ void hist_kernel(const int* __restrict__ ei) {
    int e = blockIdx.x * 256 + threadIdx.x;
    if (e < NE) atomicAdd(&g_deg[ei[e]], 1);
}

__global__ void scan1_kernel() {
    __shared__ int s[256];
    int t = threadIdx.x;
    int i = blockIdx.x * 256 + t;
    int v = (i < NN) ? g_deg[i] : 0;
    s[t] = v;
    __syncthreads();
#pragma unroll
    for (int o = 1; o < 256; o <<= 1) {
        int x = (t >= o) ? s[t - o] : 0;
        __syncthreads();
        s[t] += x;
        __syncthreads();
    }
    if (i < NN) g_rowptr[i] = s[t] - v;     // exclusive within block
    if (t == 255) g_part[blockIdx.x] = s[255];
}

__global__ void scan2_kernel() {
    __shared__ int s[256];
    int t = threadIdx.x;
    int v = (t < NB) ? g_part[t] : 0;
    s[t] = v;
    __syncthreads();
#pragma unroll
    for (int o = 1; o < 256; o <<= 1) {
        int x = (t >= o) ? s[t - o] : 0;
        __syncthreads();
        s[t] += x;
        __syncthreads();
    }
    if (t < NB) g_poff[t] = s[t] - v;       // exclusive block offsets
}

__global__ void scan3_kernel() {
    int i = blockIdx.x * 256 + threadIdx.x;
    if (i < NN) {
        int rp = g_rowptr[i] + g_poff[i >> 8];
        g_rowptr[i] = rp;
        g_cur[i] = rp;
    }
    if (i == 0) g_rowptr[NN] = NE;
}

__global__ void scatter_kernel(const int* __restrict__ ei) {
    int e = blockIdx.x * 256 + threadIdx.x;
    if (e >= NE) return;
    int r = ei[e];
    int c = ei[NE + e];
    int pos = atomicAdd(&g_cur[r], 1);
    g_ecol[pos] = c;
}

// ---------------- fused softmax + aggregate (warp per dst node) --------------
__global__ void aggregate_kernel(const float* __restrict__ bias, float* __restrict__ out) {
    int n = blockIdx.x * 8 + (threadIdx.x >> 5);
    if (n >= NN) return;
    int lane = threadIdx.x & 31;
    int beg = g_rowptr[n];
    int end = g_rowptr[n + 1];

    float4 aR = *(const float4*)(g_asrc + n * 4);

    // pass 1: per-head max of leaky_relu logits
    float4 mx = make_float4(-CUDART_INF_F, -CUDART_INF_F, -CUDART_INF_F, -CUDART_INF_F);
    for (int i = beg + lane; i < end; i += 32) {
        int c = g_ecol[i];
        float4 d = *(const float4*)(g_adst + c * 4);
        float lx = aR.x + d.x; lx = lx > 0.f ? lx : 0.2f * lx;
        float ly = aR.y + d.y; ly = ly > 0.f ? ly : 0.2f * ly;
        float lz = aR.z + d.z; lz = lz > 0.f ? lz : 0.2f * lz;
        float lw = aR.w + d.w; lw = lw > 0.f ? lw : 0.2f * lw;
        mx.x = fmaxf(mx.x, lx); mx.y = fmaxf(mx.y, ly);
        mx.z = fmaxf(mx.z, lz); mx.w = fmaxf(mx.w, lw);
    }
#pragma unroll
    for (int o = 16; o; o >>= 1) {
        mx.x = fmaxf(mx.x, __shfl_xor_sync(0xffffffffu, mx.x, o));
        mx.y = fmaxf(mx.y, __shfl_xor_sync(0xffffffffu, mx.y, o));
        mx.z = fmaxf(mx.z, __shfl_xor_sync(0xffffffffu, mx.z, o));
        mx.w = fmaxf(mx.w, __shfl_xor_sync(0xffffffffu, mx.w, o));
    }

    // pass 2: per-head sum of exp(logit - max)
    float4 sm = make_float4(0.f, 0.f, 0.f, 0.f);
    for (int i = beg + lane; i < end; i += 32) {
        int c = g_ecol[i];
        float4 d = *(const float4*)(g_adst + c * 4);
        float lx = aR.x + d.x; lx = lx > 0.f ? lx : 0.2f * lx;
        float ly = aR.y + d.y; ly = ly > 0.f ? ly : 0.2f * ly;
        float lz = aR.z + d.z; lz = lz > 0.f ? lz : 0.2f * lz;
        float lw = aR.w + d.w; lw = lw > 0.f ? lw : 0.2f * lw;
        sm.x += expf(lx - mx.x); sm.y += expf(ly - mx.y);
        sm.z += expf(lz - mx.z); sm.w += expf(lw - mx.w);
    }
#pragma unroll
    for (int o = 16; o; o >>= 1) {
        sm.x += __shfl_xor_sync(0xffffffffu, sm.x, o);
        sm.y += __shfl_xor_sync(0xffffffffu, sm.y, o);
        sm.z += __shfl_xor_sync(0xffffffffu, sm.z, o);
        sm.w += __shfl_xor_sync(0xffffffffu, sm.w, o);
    }

    // per-lane head selection (lane covers out cols lane*8 .. +7, head = lane>>3)
    int h = lane >> 3;
    float aRh  = (h == 0) ? aR.x : (h == 1) ? aR.y : (h == 2) ? aR.z : aR.w;
    float mxh  = (h == 0) ? mx.x : (h == 1) ? mx.y : (h == 2) ? mx.z : mx.w;
    float smh  = (h == 0) ? sm.x : (h == 1) ? sm.y : (h == 2) ? sm.z : sm.w;
    float invh = 1.f / fmaxf(smh, 1e-16f);

    // pass 3: weighted feature gather (warp-wide per edge)
    float4 a0 = make_float4(0.f, 0.f, 0.f, 0.f);
    float4 a1 = make_float4(0.f, 0.f, 0.f, 0.f);
    for (int i = beg; i < end; i++) {
        int c = g_ecol[i];                       // uniform across warp
        float d = g_adst[c * 4 + h];
        float l = aRh + d; l = l > 0.f ? l : 0.2f * l;
        float coef = expf(l - mxh) * invh;
        const float4* src = (const float4*)(g_xh + (long)c * OALL + lane * 8);
        float4 v0 = src[0], v1 = src[1];
        a0.x += coef * v0.x; a0.y += coef * v0.y;
        a0.z += coef * v0.z; a0.w += coef * v0.w;
        a1.x += coef * v1.x; a1.y += coef * v1.y;
        a1.z += coef * v1.z; a1.w += coef * v1.w;
    }

    const float4* bp = (const float4*)(bias + lane * 8);
    float4 b0 = bp[0], b1 = bp[1];
    a0.x += b0.x; a0.y += b0.y; a0.z += b0.z; a0.w += b0.w;
    a1.x += b1.x; a1.y += b1.y; a1.z += b1.z; a1.w += b1.w;
    float4* op = (float4*)(out + (long)n * OALL + lane * 8);
    op[0] = a0;
    op[1] = a1;
}

// -----------------------------------------------------------------------------
extern "C" void kernel_launch(void* const* d_in, const int* in_sizes, int n_in,
                              void* d_out, int out_size) {
    const float* x     = (const float*)d_in[0];
    const int*   ei    = (const int*)d_in[1];
    const float* w     = (const float*)d_in[2];
    const float* att_s = (const float*)d_in[3];
    const float* att_d = (const float*)d_in[4];
    const float* bias  = (const float*)d_in[5];
    float* out = (float*)d_out;

    // CSR build (independent of GEMM)
    zero_deg_kernel<<<NB, 256>>>();
    hist_kernel<<<(NE + 255) / 256, 256>>>(ei);
    scan1_kernel<<<NB, 256>>>();
    scan2_kernel<<<1, 256>>>();
    scan3_kernel<<<NB, 256>>>();
    scatter_kernel<<<(NE + 255) / 256, 256>>>(ei);

    // projection + attention coefficients
    gemm_kernel<<<(NN + 63) / 64, 256>>>(x, w);
    alpha_kernel<<<(NN + 7) / 8, 256>>>(att_s, att_d);

    // fused segment softmax + aggregation
    aggregate_kernel<<<(NN + 7) / 8, 256>>>(bias, out);
}

// round 7
// speedup vs baseline: 1.8215x; 1.1113x over previous
#include <cuda_runtime.h>
#include <cuda_bf16.h>
#include <math_constants.h>

#define NN 50000
#define NE 800000
#define FIN 256
#define OALL 256   /* HEADS*OUT = 4*64 */
#define NB 196     /* ceil(NN/256) */

// ---------------- scratch (static device globals; no allocation) -------------
__device__ __align__(16) float g_xh[NN * OALL];      // projected features [N,256]
__device__ __align__(16) float g_asrc[NN * 4];
__device__ __align__(16) float g_adst[NN * 4];
__device__ int g_deg[NN];
__device__ int g_rowptr[NN + 1];
__device__ int g_cur[NN];
__device__ int g_part[NB];
__device__ int g_poff[NB];
__device__ int g_ecol[NE];

// ---------------- tf32 helpers ----------------------------------------------
__device__ __forceinline__ unsigned tf32hi(float v) {
    unsigned r;
    asm("cvt.rna.tf32.f32 %0, %1;" : "=r"(r) : "f"(v));
    return r;
}

__device__ __forceinline__ void mma8(float* c, const unsigned* a, const unsigned* b) {
    asm volatile("mma.sync.aligned.m16n8k8.row.col.f32.tf32.tf32.f32 "
                 "{%0,%1,%2,%3},{%4,%5,%6,%7},{%8,%9},{%0,%1,%2,%3};"
                 : "+f"(c[0]), "+f"(c[1]), "+f"(c[2]), "+f"(c[3])
                 : "r"(a[0]), "r"(a[1]), "r"(a[2]), "r"(a[3]),
                   "r"(b[0]), "r"(b[1]));
}

// ---------------- k1: xh = x @ W via TF32x3 tensor-core MMA ------------------
#define GBM 128
#define GBN 64
#define GBK 32
#define ASTRIDE 36
#define BSTRIDE 68

__global__ void gemm_tc_kernel(const float* __restrict__ x, const float* __restrict__ w) {
    __shared__ __align__(16) float As[GBM][ASTRIDE];   // [row][k]
    __shared__ __align__(16) float Bs[GBK][BSTRIDE];   // [k][n]
    int tid  = threadIdx.x;
    int wid  = tid >> 5;
    int lane = tid & 31;
    int gid  = lane >> 2;      // groupID 0..7
    int tig  = lane & 3;       // thread-in-group 0..3
    int warpM = wid & 3;       // 0..3  -> rows warpM*32
    int warpN = wid >> 2;      // 0..1  -> cols warpN*32
    int rowBase = blockIdx.x * GBM;
    int head = blockIdx.y;

    int axRow = tid >> 1;               // 0..127
    int axK   = (tid & 1) * 16;         // 0 or 16
    int bwK   = tid >> 3;               // 0..31
    int bwC   = (tid & 7) * 8;          // 0..56

    float acc[2][4][4];
#pragma unroll
    for (int mt = 0; mt < 2; mt++)
#pragma unroll
        for (int nt = 0; nt < 4; nt++)
#pragma unroll
            for (int j = 0; j < 4; j++) acc[mt][nt][j] = 0.f;

    for (int k0 = 0; k0 < FIN; k0 += GBK) {
        {
            int grow = rowBase + axRow;
#pragma unroll
            for (int p = 0; p < 4; p++) {
                float4 v = make_float4(0.f, 0.f, 0.f, 0.f);
                if (grow < NN) v = *(const float4*)(x + (long)grow * FIN + k0 + axK + p * 4);
                *(float4*)&As[axRow][axK + p * 4] = v;
            }
        }
        {
            const float* wp = w + head * (FIN * 64) + (k0 + bwK) * 64 + bwC;
            *(float4*)&Bs[bwK][bwC]     = *(const float4*)(wp);
            *(float4*)&Bs[bwK][bwC + 4] = *(const float4*)(wp + 4);
        }
        __syncthreads();

#pragma unroll
        for (int ks = 0; ks < 4; ks++) {
            int kb = ks * 8;
            unsigned ah[2][4], al[2][4];
#pragma unroll
            for (int mt = 0; mt < 2; mt++) {
                int r0 = warpM * 32 + mt * 16 + gid;
                float v0 = As[r0][kb + tig];
                float v1 = As[r0 + 8][kb + tig];
                float v2 = As[r0][kb + tig + 4];
                float v3 = As[r0 + 8][kb + tig + 4];
                ah[mt][0] = tf32hi(v0); al[mt][0] = __float_as_uint(v0 - __uint_as_float(ah[mt][0]));
                ah[mt][1] = tf32hi(v1); al[mt][1] = __float_as_uint(v1 - __uint_as_float(ah[mt][1]));
                ah[mt][2] = tf32hi(v2); al[mt][2] = __float_as_uint(v2 - __uint_as_float(ah[mt][2]));
                ah[mt][3] = tf32hi(v3); al[mt][3] = __float_as_uint(v3 - __uint_as_float(ah[mt][3]));
            }
            unsigned bh[4][2], bl[4][2];
#pragma unroll
            for (int nt = 0; nt < 4; nt++) {
                int n = warpN * 32 + nt * 8 + gid;
                float v0 = Bs[kb + tig][n];
                float v1 = Bs[kb + tig + 4][n];
                bh[nt][0] = tf32hi(v0); bl[nt][0] = __float_as_uint(v0 - __uint_as_float(bh[nt][0]));
                bh[nt][1] = tf32hi(v1); bl[nt][1] = __float_as_uint(v1 - __uint_as_float(bh[nt][1]));
            }
#pragma unroll
            for (int mt = 0; mt < 2; mt++)
#pragma unroll
                for (int nt = 0; nt < 4; nt++) {
                    mma8(acc[mt][nt], ah[mt], bh[nt]);   // hi*hi
                    mma8(acc[mt][nt], ah[mt], bl[nt]);   // hi*lo
                    mma8(acc[mt][nt], al[mt], bh[nt]);   // lo*hi
                }
        }
        __syncthreads();
    }

#pragma unroll
    for (int mt = 0; mt < 2; mt++) {
        int r0 = rowBase + warpM * 32 + mt * 16 + gid;
#pragma unroll
        for (int nt = 0; nt < 4; nt++) {
            int col = head * 64 + warpN * 32 + nt * 8 + 2 * tig;
            if (r0 < NN)
                *(float2*)(g_xh + (long)r0 * OALL + col) = make_float2(acc[mt][nt][0], acc[mt][nt][1]);
            if (r0 + 8 < NN)
                *(float2*)(g_xh + (long)(r0 + 8) * OALL + col) = make_float2(acc[mt][nt][2], acc[mt][nt][3]);
        }
    }
}

// ---------------- k2: alpha_src/dst[n,h] = <xh[n,h,:], att[h,:]> -------------
__global__ void alpha_kernel(const float* __restrict__ att_s, const float* __restrict__ att_d) {
    int n = blockIdx.x * 8 + (threadIdx.x >> 5);
    if (n >= NN) return;
    int lane = threadIdx.x & 31;
    int base = lane * 8;
    int h = lane >> 3;

    const float4* xr = (const float4*)(g_xh + (long)n * OALL + base);
    const float4* sa = (const float4*)(att_s + base);
    const float4* da = (const float4*)(att_d + base);
    float4 v0 = xr[0], v1 = xr[1];
    float4 s0 = sa[0], s1 = sa[1];
    float4 d0 = da[0], d1 = da[1];

    float s = v0.x * s0.x + v0.y * s0.y + v0.z * s0.z + v0.w * s0.w
            + v1.x * s1.x + v1.y * s1.y + v1.z * s1.z + v1.w * s1.w;
    float d = v0.x * d0.x + v0.y * d0.y + v0.z * d0.z + v0.w * d0.w
            + v1.x * d1.x + v1.y * d1.y + v1.z * d1.z + v1.w * d1.w;
#pragma unroll
    for (int o = 4; o; o >>= 1) {
        s += __shfl_xor_sync(0xffffffffu, s, o);
        d += __shfl_xor_sync(0xffffffffu, d, o);
    }
    if ((lane & 7) == 0) {
        g_asrc[n * 4 + h] = s;
        g_adst[n * 4 + h] = d;
    }
}

// ---------------- CSR build --------------------------------------------------
__global__ void zero_deg_kernel() {
    int i = blockIdx.x * 256 + threadIdx.x;
    if (i < NN) g_deg[i] = 0;
}

__global__ void hist_kernel(const int* __restrict__ ei) {
    int e = blockIdx.x * 256 + threadIdx.x;
    if (e < NE) atomicAdd(&g_deg[ei[e]], 1);
}

__global__ void scan1_kernel() {
    __shared__ int s[256];
    int t = threadIdx.x;
    int i = blockIdx.x * 256 + t;
    int v = (i < NN) ? g_deg[i] : 0;
    s[t] = v;
    __syncthreads();
#pragma unroll
    for (int o = 1; o < 256; o <<= 1) {
        int x = (t >= o) ? s[t - o] : 0;
        __syncthreads();
        s[t] += x;
        __syncthreads();
    }
    if (i < NN) g_rowptr[i] = s[t] - v;
    if (t == 255) g_part[blockIdx.x] = s[255];
}

__global__ void scan2_kernel() {
    __shared__ int s[256];
    int t = threadIdx.x;
    int v = (t < NB) ? g_part[t] : 0;
    s[t] = v;
    __syncthreads();
#pragma unroll
    for (int o = 1; o < 256; o <<= 1) {
        int x = (t >= o) ? s[t - o] : 0;
        __syncthreads();
        s[t] += x;
        __syncthreads();
    }
    if (t < NB) g_poff[t] = s[t] - v;
}

__global__ void scan3_kernel() {
    int i = blockIdx.x * 256 + threadIdx.x;
    if (i < NN) {
        int rp = g_rowptr[i] + g_poff[i >> 8];
        g_rowptr[i] = rp;
        g_cur[i] = rp;
    }
    if (i == 0) g_rowptr[NN] = NE;
}

__global__ void scatter_kernel(const int* __restrict__ ei) {
    int e = blockIdx.x * 256 + threadIdx.x;
    if (e >= NE) return;
    int r = ei[e];
    int c = ei[NE + e];
    int pos = atomicAdd(&g_cur[r], 1);
    g_ecol[pos] = c;
}

// ---------------- fused softmax + aggregate (warp per dst node) --------------
__global__ void aggregate_kernel(const float* __restrict__ bias, float* __restrict__ out) {
    int n = blockIdx.x * 8 + (threadIdx.x >> 5);
    if (n >= NN) return;
    int lane = threadIdx.x & 31;
    int beg = g_rowptr[n];
    int end = g_rowptr[n + 1];

    float4 aR = *(const float4*)(g_asrc + n * 4);

    float4 mx = make_float4(-CUDART_INF_F, -CUDART_INF_F, -CUDART_INF_F, -CUDART_INF_F);
    for (int i = beg + lane; i < end; i += 32) {
        int c = g_ecol[i];
        float4 d = *(const float4*)(g_adst + c * 4);
        float lx = aR.x + d.x; lx = lx > 0.f ? lx : 0.2f * lx;
        float ly = aR.y + d.y; ly = ly > 0.f ? ly : 0.2f * ly;
        float lz = aR.z + d.z; lz = lz > 0.f ? lz : 0.2f * lz;
        float lw = aR.w + d.w; lw = lw > 0.f ? lw : 0.2f * lw;
        mx.x = fmaxf(mx.x, lx); mx.y = fmaxf(mx.y, ly);
        mx.z = fmaxf(mx.z, lz); mx.w = fmaxf(mx.w, lw);
    }
#pragma unroll
    for (int o = 16; o; o >>= 1) {
        mx.x = fmaxf(mx.x, __shfl_xor_sync(0xffffffffu, mx.x, o));
        mx.y = fmaxf(mx.y, __shfl_xor_sync(0xffffffffu, mx.y, o));
        mx.z = fmaxf(mx.z, __shfl_xor_sync(0xffffffffu, mx.z, o));
        mx.w = fmaxf(mx.w, __shfl_xor_sync(0xffffffffu, mx.w, o));
    }

    float4 sm = make_float4(0.f, 0.f, 0.f, 0.f);
    for (int i = beg + lane; i < end; i += 32) {
        int c = g_ecol[i];
        float4 d = *(const float4*)(g_adst + c * 4);
        float lx = aR.x + d.x; lx = lx > 0.f ? lx : 0.2f * lx;
        float ly = aR.y + d.y; ly = ly > 0.f ? ly : 0.2f * ly;
        float lz = aR.z + d.z; lz = lz > 0.f ? lz : 0.2f * lz;
        float lw = aR.w + d.w; lw = lw > 0.f ? lw : 0.2f * lw;
        sm.x += expf(lx - mx.x); sm.y += expf(ly - mx.y);
        sm.z += expf(lz - mx.z); sm.w += expf(lw - mx.w);
    }
#pragma unroll
    for (int o = 16; o; o >>= 1) {
        sm.x += __shfl_xor_sync(0xffffffffu, sm.x, o);
        sm.y += __shfl_xor_sync(0xffffffffu, sm.y, o);
        sm.z += __shfl_xor_sync(0xffffffffu, sm.z, o);
        sm.w += __shfl_xor_sync(0xffffffffu, sm.w, o);
    }

    int h = lane >> 3;
    float aRh  = (h == 0) ? aR.x : (h == 1) ? aR.y : (h == 2) ? aR.z : aR.w;
    float mxh  = (h == 0) ? mx.x : (h == 1) ? mx.y : (h == 2) ? mx.z : mx.w;
    float smh  = (h == 0) ? sm.x : (h == 1) ? sm.y : (h == 2) ? sm.z : sm.w;
    float invh = 1.f / fmaxf(smh, 1e-16f);

    float4 a0 = make_float4(0.f, 0.f, 0.f, 0.f);
    float4 a1 = make_float4(0.f, 0.f, 0.f, 0.f);
    for (int i = beg; i < end; i++) {
        int c = g_ecol[i];
        float d = g_adst[c * 4 + h];
        float l = aRh + d; l = l > 0.f ? l : 0.2f * l;
        float coef = expf(l - mxh) * invh;
        const float4* src = (const float4*)(g_xh + (long)c * OALL + lane * 8);
        float4 v0 = src[0], v1 = src[1];
        a0.x += coef * v0.x; a0.y += coef * v0.y;
        a0.z += coef * v0.z; a0.w += coef * v0.w;
        a1.x += coef * v1.x; a1.y += coef * v1.y;
        a1.z += coef * v1.z; a1.w += coef * v1.w;
    }

    const float4* bp = (const float4*)(bias + lane * 8);
    float4 b0 = bp[0], b1 = bp[1];
    a0.x += b0.x; a0.y += b0.y; a0.z += b0.z; a0.w += b0.w;
    a1.x += b1.x; a1.y += b1.y; a1.z += b1.z; a1.w += b1.w;
    float4* op = (float4*)(out + (long)n * OALL + lane * 8);
    op[0] = a0;
    op[1] = a1;
}

// -----------------------------------------------------------------------------
extern "C" void kernel_launch(void* const* d_in, const int* in_sizes, int n_in,
                              void* d_out, int out_size) {
    const float* x     = (const float*)d_in[0];
    const int*   ei    = (const int*)d_in[1];
    const float* w     = (const float*)d_in[2];
    const float* att_s = (const float*)d_in[3];
    const float* att_d = (const float*)d_in[4];
    const float* bias  = (const float*)d_in[5];
    float* out = (float*)d_out;

    zero_deg_kernel<<<NB, 256>>>();
    hist_kernel<<<(NE + 255) / 256, 256>>>(ei);
    scan1_kernel<<<NB, 256>>>();
    scan2_kernel<<<1, 256>>>();
    scan3_kernel<<<NB, 256>>>();
    scatter_kernel<<<(NE + 255) / 256, 256>>>(ei);

    gemm_tc_kernel<<<dim3((NN + GBM - 1) / GBM, 4), 256>>>(x, w);
    alpha_kernel<<<(NN + 7) / 8, 256>>>(att_s, att_d);

    aggregate_kernel<<<(NN + 7) / 8, 256>>>(bias, out);
}